// round 9
// baseline (speedup 1.0000x reference)
#include <cuda_runtime.h>
#include <cuda_bf16.h>
#include <math.h>
#include <stdint.h>

#define NUM_C   100
#define CPAD    128
#define DIM     256
#define TEMPV   0.7f
#define EPSV    1e-8f
#define NROWS   8192
#define SCTA    32            // k_scatter CTAs
#define SROWS   256           // rows per scatter CTA

// B smem: padded row stride 264 bf16 = 528 bytes (132 words -> conflict-free ldmatrix)
#define BSTRIDE 528
#define BH_SIZE (CPAD * BSTRIDE)       // 67584

// ---------------- device scratch ----------------
__device__ float g_part[SCTA * CPAD * DIM];   // per-CTA class-sum slabs (4.2 MB)
__device__ float g_cpart[SCTA * CPAD];        // per-CTA class counts
__device__ float g_countf[CPAD];
__device__ __align__(16) __nv_bfloat16 g_pTh[CPAD * DIM];   // protoT (bf16)
__device__ float g_ss[NROWS];                 // per-row |f|^2
__device__ int   g_is64;

// ---------------- helpers ----------------
__device__ __forceinline__ uint32_t smem_u32(const void* p) {
    uint32_t a;
    asm("{ .reg .u64 t; cvta.to.shared.u64 t, %1; cvt.u32.u64 %0, t; }" : "=r"(a) : "l"(p));
    return a;
}
__device__ __forceinline__ int get_label(const void* lab, int i, int is64) {
    return is64 ? (int)((const long long*)lab)[i] : ((const int*)lab)[i];
}
__device__ __forceinline__ void split2(float2 v, uint32_t& h, uint32_t& l) {
    __nv_bfloat16 hx = __float2bfloat16(v.x), hy = __float2bfloat16(v.y);
    float rx = v.x - __bfloat162float(hx);
    float ry = v.y - __bfloat162float(hy);
    __nv_bfloat162 H, L;
    H.x = hx; H.y = hy;
    L.x = __float2bfloat16(rx); L.y = __float2bfloat16(ry);
    h = *(uint32_t*)&H;
    l = *(uint32_t*)&L;
}
__device__ __forceinline__ void mma_bf16(float* d, const uint32_t* a, const uint32_t* b) {
    asm volatile(
        "mma.sync.aligned.m16n8k16.row.col.f32.bf16.bf16.f32 "
        "{%0,%1,%2,%3}, {%4,%5,%6,%7}, {%8,%9}, {%0,%1,%2,%3};"
        : "+f"(d[0]), "+f"(d[1]), "+f"(d[2]), "+f"(d[3])
        : "r"(a[0]), "r"(a[1]), "r"(a[2]), "r"(a[3]), "r"(b[0]), "r"(b[1]));
}
#define LDSM4(r, a) \
    asm volatile("ldmatrix.sync.aligned.m8n8.x4.shared.b16 {%0,%1,%2,%3}, [%4];" \
        : "=r"((r)[0]), "=r"((r)[1]), "=r"((r)[2]), "=r"((r)[3]) : "r"(a))

// ---------------- K0: detect label dtype + zero output ----------------
__global__ void k_init(const int* lab32, int n, float* out) {
    int t = threadIdx.x;
    __shared__ int sflag[256];
    int fl = 0;
    int half = n >> 1;
    for (int i = t; i < half; i += 256) fl |= lab32[2 * i + 1];
    sflag[t] = fl;
    __syncthreads();
    for (int s = 128; s > 0; s >>= 1) { if (t < s) sflag[t] |= sflag[t + s]; __syncthreads(); }
    if (t == 0) { g_is64 = (sflag[0] == 0) ? 1 : 0; out[0] = 0.f; }
}

// ---------------- K1: smem-staged class sums + counts + row norms ----------------
// 32 CTAs x 256 threads; each warp owns 32 rows, one row per iteration (coalesced).
__global__ void __launch_bounds__(256, 1)
k_scatter(const float* __restrict__ f, const void* __restrict__ lab) {
    extern __shared__ float sp[];           // CPAD*DIM partial sums
    __shared__ float scnt[CPAD];
    int t = threadIdx.x, wid = t >> 5, lid = t & 31;
    for (int i = t; i < CPAD * DIM; i += 256) sp[i] = 0.f;
    if (t < CPAD) scnt[t] = 0.f;
    __syncthreads();
    int is64 = g_is64;
    int rowbase = blockIdx.x * SROWS + wid * 32;
    for (int rr = 0; rr < 32; rr++) {
        int row = rowbase + rr;
        const float4* fr = (const float4*)(f + (size_t)row * DIM);
        float4 v0 = fr[lid];
        float4 v1 = fr[32 + lid];
        int c = 0;
        if (lid == 0) c = get_label(lab, row, is64);
        c = __shfl_sync(0xffffffffu, c, 0);
        float* dst = sp + c * DIM;
        atomicAdd(dst + lid * 4 + 0, v0.x);
        atomicAdd(dst + lid * 4 + 1, v0.y);
        atomicAdd(dst + lid * 4 + 2, v0.z);
        atomicAdd(dst + lid * 4 + 3, v0.w);
        atomicAdd(dst + 128 + lid * 4 + 0, v1.x);
        atomicAdd(dst + 128 + lid * 4 + 1, v1.y);
        atomicAdd(dst + 128 + lid * 4 + 2, v1.z);
        atomicAdd(dst + 128 + lid * 4 + 3, v1.w);
        float ss = v0.x*v0.x + v0.y*v0.y + v0.z*v0.z + v0.w*v0.w
                 + v1.x*v1.x + v1.y*v1.y + v1.z*v1.z + v1.w*v1.w;
        #pragma unroll
        for (int o = 16; o > 0; o >>= 1) ss += __shfl_xor_sync(0xffffffffu, ss, o);
        if (lid == 0) { g_ss[row] = ss; atomicAdd(&scnt[c], 1.0f); }
    }
    __syncthreads();
    float* slab = g_part + (size_t)blockIdx.x * (CPAD * DIM);
    for (int i = t; i < CPAD * DIM; i += 256) slab[i] = sp[i];
    if (t < CPAD) g_cpart[blockIdx.x * CPAD + t] = scnt[t];
}

// ---------------- K2: reduce slabs, protoT = proto/(|proto|*T) as bf16 ----------------
__global__ void k_proto() {
    int c = blockIdx.x, t = threadIdx.x;
    float s = 0.f;
    #pragma unroll 8
    for (int b = 0; b < SCTA; b++) s += g_part[b * (CPAD * DIM) + c * DIM + t];
    float cnt = 0.f;
    #pragma unroll 8
    for (int b = 0; b < SCTA; b++) cnt += g_cpart[b * CPAD + c];
    float p = s / fmaxf(cnt, 1.0f);
    __shared__ float red[256];
    red[t] = p * p;
    __syncthreads();
    for (int st = 128; st > 0; st >>= 1) { if (t < st) red[t] += red[t + st]; __syncthreads(); }
    float nrm = fmaxf(sqrtf(red[0]), EPSV);
    g_pTh[c * DIM + t] = __float2bfloat16(p / (nrm * TEMPV));
    if (t == 0) g_countf[c] = cnt;
}

// ---------------- K3: HMMA (fp32A x bf16B) GEMM + fused contrastive epilogue ----------------
// 128 CTAs x 256 threads. Warp w: row-tile (w&3)*16, class half (w>>2)*64.
__global__ void __launch_bounds__(256, 1)
k_main(const float* __restrict__ f, const void* __restrict__ lab, float* out, int n) {
    extern __shared__ char dsm[];               // Bh: 67584
    __shared__ float cnt_sh[CPAD];
    __shared__ float invfn_sh[64];
    __shared__ int   lab_sh[64];
    __shared__ float rs_part[128];
    __shared__ float dg_part[128];
    __shared__ float red_sh[2];

    int t = threadIdx.x, wid = t >> 5, lid = t & 31;
    int g = lid >> 2, tq = lid & 3;
    int wtile = wid & 3, half = wid >> 2;
    int row0 = blockIdx.x * 64;

    // fill protoT smem (padded stride, conflict-free)
    const uint4* gh = (const uint4*)g_pTh;
    for (int idx = t; idx < CPAD * 32; idx += 256) {
        int r = idx >> 5, c = idx & 31;
        *(uint4*)(dsm + r * BSTRIDE + c * 16) = gh[idx];
    }
    if (t < CPAD) cnt_sh[t] = g_countf[t];
    if (t < 64) {
        invfn_sh[t] = 1.0f / fmaxf(sqrtf(g_ss[row0 + t]), EPSV);
        lab_sh[t] = get_label(lab, row0 + t, g_is64);
    }
    __syncthreads();

    uint32_t Bh_u = smem_u32(dsm) + (uint32_t)(half * 64 * BSTRIDE);
    int m8 = lid >> 3, j8 = lid & 7;
    uint32_t laneoff = (uint32_t)(((m8 >> 1) * 8 + j8) * BSTRIDE + (m8 & 1) * 16);

    int wr0 = wtile * 16 + g;
    const float* fr0 = f + (size_t)(row0 + wr0) * DIM;
    const float* fr1 = fr0 + 8 * DIM;

    float acc[8][4];
    #pragma unroll
    for (int i = 0; i < 8; i++) { acc[i][0] = acc[i][1] = acc[i][2] = acc[i][3] = 0.f; }

    // A register double-buffer (distance-1 prefetch)
    float2 abuf[2][4];
    {
        int k0 = 2 * tq;
        abuf[0][0] = *(const float2*)(fr0 + k0);
        abuf[0][1] = *(const float2*)(fr1 + k0);
        abuf[0][2] = *(const float2*)(fr0 + k0 + 8);
        abuf[0][3] = *(const float2*)(fr1 + k0 + 8);
    }

    #pragma unroll 4
    for (int kt = 0; kt < 16; kt++) {
        int cb = kt & 1;
        if (kt < 15) {
            int k0 = (kt + 1) * 16 + 2 * tq;
            abuf[cb ^ 1][0] = *(const float2*)(fr0 + k0);
            abuf[cb ^ 1][1] = *(const float2*)(fr1 + k0);
            abuf[cb ^ 1][2] = *(const float2*)(fr0 + k0 + 8);
            abuf[cb ^ 1][3] = *(const float2*)(fr1 + k0 + 8);
        }
        uint32_t ah[4], al[4];
        #pragma unroll
        for (int i = 0; i < 4; i++) split2(abuf[cb][i], ah[i], al[i]);

        uint32_t kb = (uint32_t)(kt * 32) + laneoff;
        uint32_t bh[4][4];
        #pragma unroll
        for (int ntp = 0; ntp < 4; ntp++)
            LDSM4(bh[ntp], Bh_u + (uint32_t)(ntp * 16 * BSTRIDE) + kb);
        #pragma unroll
        for (int ntp = 0; ntp < 4; ntp++) {
            mma_bf16(acc[2 * ntp],     ah, bh[ntp]);
            mma_bf16(acc[2 * ntp + 1], ah, bh[ntp] + 2);
            mma_bf16(acc[2 * ntp],     al, bh[ntp]);
            mma_bf16(acc[2 * ntp + 1], al, bh[ntp] + 2);
        }
    }

    // ---- epilogue: partial row sums over this warp's 64 classes ----
    int chb = half * 64;
    float ifn0 = invfn_sh[wr0], ifn1 = invfn_sh[wr0 + 8];
    int   lb0  = lab_sh[wr0],   lb1  = lab_sh[wr0 + 8];
    float rs0 = 0.f, rs1 = 0.f, dg0 = 0.f, dg1 = 0.f;
    #pragma unroll
    for (int nt = 0; nt < 8; nt++) {
        #pragma unroll
        for (int cc = 0; cc < 2; cc++) {
            int cls = chb + nt * 8 + 2 * tq + cc;
            float cw = cnt_sh[cls];
            float v0 = acc[nt][cc]     * ifn0;
            float v1 = acc[nt][2 + cc] * ifn1;
            rs0 += cw * __expf(v0);
            rs1 += cw * __expf(v1);
            if (cls == lb0) dg0 = v0;
            if (cls == lb1) dg1 = v1;
        }
    }
    #pragma unroll
    for (int o = 1; o <= 2; o <<= 1) {
        rs0 += __shfl_xor_sync(0xffffffffu, rs0, o);
        rs1 += __shfl_xor_sync(0xffffffffu, rs1, o);
        dg0 += __shfl_xor_sync(0xffffffffu, dg0, o);
        dg1 += __shfl_xor_sync(0xffffffffu, dg1, o);
    }
    if (tq == 0) {
        rs_part[half * 64 + wr0]     = rs0;
        rs_part[half * 64 + wr0 + 8] = rs1;
        dg_part[half * 64 + wr0]     = dg0;
        dg_part[half * 64 + wr0 + 8] = dg1;
    }
    __syncthreads();

    if (t < 64) {
        float lr = logf(rs_part[t] + rs_part[64 + t]) - (dg_part[t] + dg_part[64 + t]);
        #pragma unroll
        for (int o = 16; o > 0; o >>= 1) lr += __shfl_down_sync(0xffffffffu, lr, o);
        if (lid == 0) red_sh[wid] = lr;
    }
    __syncthreads();
    if (t == 0) atomicAdd(out, (red_sh[0] + red_sh[1]) / (float)n);
}

// ---------------- launch ----------------
extern "C" void kernel_launch(void* const* d_in, const int* in_sizes, int n_in,
                              void* d_out, int out_size) {
    const float* f = (const float*)d_in[0];
    const void*  lab = d_in[1];
    float* out = (float*)d_out;
    int n = in_sizes[1];   // 8192

    cudaFuncSetAttribute(k_scatter, cudaFuncAttributeMaxDynamicSharedMemorySize, CPAD * DIM * 4);
    cudaFuncSetAttribute(k_main, cudaFuncAttributeMaxDynamicSharedMemorySize, BH_SIZE);

    k_init<<<1, 256>>>((const int*)lab, n, out);
    k_scatter<<<SCTA, 256, CPAD * DIM * 4>>>(f, lab);
    k_proto<<<CPAD, 256>>>();
    k_main<<<n / 64, 256, BH_SIZE>>>(f, lab, out, n);
}

// round 10
// speedup vs baseline: 2.1599x; 2.1599x over previous
#include <cuda_runtime.h>
#include <cuda_bf16.h>
#include <math.h>
#include <stdint.h>

#define NUM_C   100
#define CPAD    128
#define DIM     256
#define TEMPV   0.7f
#define EPSV    1e-8f
#define NROWS   8192

// B smem: padded row stride 264 bf16 = 528 bytes (conflict-free ldmatrix)
#define BSTRIDE 528
#define BH_SIZE (CPAD * BSTRIDE)       // 67584

// ---------------- device scratch ----------------
__device__ float g_countf[CPAD];
__device__ __align__(16) __nv_bfloat16 g_pTh[CPAD * DIM];   // protoT (bf16)
__device__ int   g_is64;

// ---------------- helpers ----------------
__device__ __forceinline__ uint32_t smem_u32(const void* p) {
    uint32_t a;
    asm("{ .reg .u64 t; cvta.to.shared.u64 t, %1; cvt.u32.u64 %0, t; }" : "=r"(a) : "l"(p));
    return a;
}
__device__ __forceinline__ int get_label(const void* lab, int i, int is64) {
    return is64 ? (int)((const long long*)lab)[i] : ((const int*)lab)[i];
}
__device__ __forceinline__ void split2(float2 v, uint32_t& h, uint32_t& l) {
    __nv_bfloat16 hx = __float2bfloat16(v.x), hy = __float2bfloat16(v.y);
    float rx = v.x - __bfloat162float(hx);
    float ry = v.y - __bfloat162float(hy);
    __nv_bfloat162 H, L;
    H.x = hx; H.y = hy;
    L.x = __float2bfloat16(rx); L.y = __float2bfloat16(ry);
    h = *(uint32_t*)&H;
    l = *(uint32_t*)&L;
}
__device__ __forceinline__ void mma_bf16(float* d, const uint32_t* a, const uint32_t* b) {
    asm volatile(
        "mma.sync.aligned.m16n8k16.row.col.f32.bf16.bf16.f32 "
        "{%0,%1,%2,%3}, {%4,%5,%6,%7}, {%8,%9}, {%0,%1,%2,%3};"
        : "+f"(d[0]), "+f"(d[1]), "+f"(d[2]), "+f"(d[3])
        : "r"(a[0]), "r"(a[1]), "r"(a[2]), "r"(a[3]), "r"(b[0]), "r"(b[1]));
}
#define LDSM4(r, a) \
    asm volatile("ldmatrix.sync.aligned.m8n8.x4.shared.b16 {%0,%1,%2,%3}, [%4];" \
        : "=r"((r)[0]), "=r"((r)[1]), "=r"((r)[2]), "=r"((r)[3]) : "r"(a))

// ---------------- K1: one CTA per class — gather, mean, normalize, emit bf16 ----------------
__global__ void __launch_bounds__(256, 1)
k_protos(const float* __restrict__ f, const void* __restrict__ lab, int n, float* out) {
    __shared__ int   list[NROWS];
    __shared__ float wacc[8][DIM];
    __shared__ float red[256];
    __shared__ int   s_m;

    int t = threadIdx.x, wid = t >> 5, lid = t & 31;
    int c = blockIdx.x;
    if (t == 0) s_m = 0;
    __syncthreads();

    // local label-dtype detection (odd 32-bit words all zero <=> int64 labels in [0,100))
    const int* l32 = (const int*)lab;
    int fl = 0;
    for (int i = t; i < (n >> 1); i += 256) fl |= l32[2 * i + 1];
    int is64 = (__syncthreads_or(fl) == 0);
    if (c == 0 && t == 0) { g_is64 = is64; out[0] = 0.f; }

    // scan labels, collect matching row ids
    for (int i = t; i < n; i += 256) {
        int li = is64 ? (int)((const long long*)lab)[i] : l32[i];
        if (li == c) { int p = atomicAdd(&s_m, 1); list[p] = i; }
    }
    __syncthreads();
    int m = s_m;

    // accumulate rows: 8 warps, 4 rows per warp per pass (batched loads for MLP)
    float s[8];
    #pragma unroll
    for (int i = 0; i < 8; i++) s[i] = 0.f;
    for (int j0 = 0; j0 < m; j0 += 32) {
        float4 va[4], vb[4];
        #pragma unroll
        for (int i = 0; i < 4; i++) {
            int j = j0 + wid * 4 + i;
            if (j < m) {
                const float* fr = f + (size_t)list[j] * DIM;
                va[i] = *(const float4*)(fr + lid * 4);
                vb[i] = *(const float4*)(fr + 128 + lid * 4);
            } else {
                va[i] = make_float4(0.f, 0.f, 0.f, 0.f);
                vb[i] = va[i];
            }
        }
        #pragma unroll
        for (int i = 0; i < 4; i++) {
            s[0] += va[i].x; s[1] += va[i].y; s[2] += va[i].z; s[3] += va[i].w;
            s[4] += vb[i].x; s[5] += vb[i].y; s[6] += vb[i].z; s[7] += vb[i].w;
        }
    }
    wacc[wid][lid * 4 + 0] = s[0];
    wacc[wid][lid * 4 + 1] = s[1];
    wacc[wid][lid * 4 + 2] = s[2];
    wacc[wid][lid * 4 + 3] = s[3];
    wacc[wid][128 + lid * 4 + 0] = s[4];
    wacc[wid][128 + lid * 4 + 1] = s[5];
    wacc[wid][128 + lid * 4 + 2] = s[6];
    wacc[wid][128 + lid * 4 + 3] = s[7];
    __syncthreads();

    float p = 0.f;
    #pragma unroll
    for (int w = 0; w < 8; w++) p += wacc[w][t];
    float cm = (float)m;
    p = p / fmaxf(cm, 1.0f);

    red[t] = p * p;
    __syncthreads();
    for (int st = 128; st > 0; st >>= 1) { if (t < st) red[t] += red[t + st]; __syncthreads(); }
    float nrm = fmaxf(sqrtf(red[0]), EPSV);
    g_pTh[c * DIM + t] = __float2bfloat16(p / (nrm * TEMPV));
    if (t == 0) g_countf[c] = cm;
}

// ---------------- K2: HMMA (fp32A-split x bf16B) + fused contrastive epilogue ----------------
// 128 CTAs x 256 threads. Warp w: row-tile (w&3)*16, class half (w>>2)*64.
__global__ void __launch_bounds__(256, 1)
k_main(const float* __restrict__ f, const void* __restrict__ lab, float* out, int n) {
    extern __shared__ char dsm[];               // Bh: 67584
    __shared__ float cnt_sh[CPAD];
    __shared__ int   lab_sh[64];
    __shared__ float rs_part[128];
    __shared__ float dg_part[128];
    __shared__ float red_sh[2];

    int t = threadIdx.x, wid = t >> 5, lid = t & 31;
    int g = lid >> 2, tq = lid & 3;
    int wtile = wid & 3, half = wid >> 2;
    int row0 = blockIdx.x * 64;

    // fill protoT smem (padded stride, conflict-free)
    const uint4* gh = (const uint4*)g_pTh;
    for (int idx = t; idx < CPAD * 32; idx += 256) {
        int r = idx >> 5, c = idx & 31;
        *(uint4*)(dsm + r * BSTRIDE + c * 16) = gh[idx];
    }
    if (t < CPAD) cnt_sh[t] = g_countf[t];
    if (t < 64) lab_sh[t] = get_label(lab, row0 + t, g_is64);
    __syncthreads();

    uint32_t Bh_u = smem_u32(dsm) + (uint32_t)(half * 64 * BSTRIDE);
    int m8 = lid >> 3, j8 = lid & 7;
    uint32_t laneoff = (uint32_t)(((m8 >> 1) * 8 + j8) * BSTRIDE + (m8 & 1) * 16);

    int wr0 = wtile * 16 + g;
    const float* fr0 = f + (size_t)(row0 + wr0) * DIM;
    const float* fr1 = fr0 + 8 * DIM;

    float acc[8][4];
    #pragma unroll
    for (int i = 0; i < 8; i++) { acc[i][0] = acc[i][1] = acc[i][2] = acc[i][3] = 0.f; }

    // A register ring, prefetch distance 2
    float2 abuf[3][4];
    #pragma unroll
    for (int pk = 0; pk < 2; pk++) {
        int k0 = pk * 16 + 2 * tq;
        abuf[pk][0] = *(const float2*)(fr0 + k0);
        abuf[pk][1] = *(const float2*)(fr1 + k0);
        abuf[pk][2] = *(const float2*)(fr0 + k0 + 8);
        abuf[pk][3] = *(const float2*)(fr1 + k0 + 8);
    }

    float ss0 = 0.f, ss1 = 0.f;                 // row |f|^2 partials (exact fp32)

    #pragma unroll
    for (int kt = 0; kt < 16; kt++) {
        int rb = kt % 3;
        if (kt < 14) {
            int wb = (kt + 2) % 3;
            int k0 = (kt + 2) * 16 + 2 * tq;
            abuf[wb][0] = *(const float2*)(fr0 + k0);
            abuf[wb][1] = *(const float2*)(fr1 + k0);
            abuf[wb][2] = *(const float2*)(fr0 + k0 + 8);
            abuf[wb][3] = *(const float2*)(fr1 + k0 + 8);
        }
        float2 a0 = abuf[rb][0], a1 = abuf[rb][1], a2 = abuf[rb][2], a3 = abuf[rb][3];
        ss0 += a0.x * a0.x + a0.y * a0.y + a2.x * a2.x + a2.y * a2.y;
        ss1 += a1.x * a1.x + a1.y * a1.y + a3.x * a3.x + a3.y * a3.y;

        uint32_t ah[4], al[4];
        split2(a0, ah[0], al[0]);
        split2(a1, ah[1], al[1]);
        split2(a2, ah[2], al[2]);
        split2(a3, ah[3], al[3]);

        uint32_t kb = (uint32_t)(kt * 32) + laneoff;
        uint32_t bh[4][4];
        #pragma unroll
        for (int ntp = 0; ntp < 4; ntp++)
            LDSM4(bh[ntp], Bh_u + (uint32_t)(ntp * 16 * BSTRIDE) + kb);
        #pragma unroll
        for (int ntp = 0; ntp < 4; ntp++) {
            mma_bf16(acc[2 * ntp],     ah, bh[ntp]);
            mma_bf16(acc[2 * ntp + 1], ah, bh[ntp] + 2);
            mma_bf16(acc[2 * ntp],     al, bh[ntp]);
            mma_bf16(acc[2 * ntp + 1], al, bh[ntp] + 2);
        }
    }

    // complete row norms within the quad (lanes differ only in tq = lid&3)
    ss0 += __shfl_xor_sync(0xffffffffu, ss0, 1);
    ss0 += __shfl_xor_sync(0xffffffffu, ss0, 2);
    ss1 += __shfl_xor_sync(0xffffffffu, ss1, 1);
    ss1 += __shfl_xor_sync(0xffffffffu, ss1, 2);
    float ifn0 = 1.0f / fmaxf(sqrtf(ss0), EPSV);
    float ifn1 = 1.0f / fmaxf(sqrtf(ss1), EPSV);

    // ---- epilogue: partial row sums over this warp's 64 classes ----
    int chb = half * 64;
    int lb0 = lab_sh[wr0], lb1 = lab_sh[wr0 + 8];
    float rs0 = 0.f, rs1 = 0.f, dg0 = 0.f, dg1 = 0.f;
    #pragma unroll
    for (int nt = 0; nt < 8; nt++) {
        #pragma unroll
        for (int cc = 0; cc < 2; cc++) {
            int cls = chb + nt * 8 + 2 * tq + cc;
            float cw = cnt_sh[cls];
            float v0 = acc[nt][cc]     * ifn0;
            float v1 = acc[nt][2 + cc] * ifn1;
            rs0 += cw * __expf(v0);
            rs1 += cw * __expf(v1);
            if (cls == lb0) dg0 = v0;
            if (cls == lb1) dg1 = v1;
        }
    }
    #pragma unroll
    for (int o = 1; o <= 2; o <<= 1) {
        rs0 += __shfl_xor_sync(0xffffffffu, rs0, o);
        rs1 += __shfl_xor_sync(0xffffffffu, rs1, o);
        dg0 += __shfl_xor_sync(0xffffffffu, dg0, o);
        dg1 += __shfl_xor_sync(0xffffffffu, dg1, o);
    }
    if (tq == 0) {
        rs_part[half * 64 + wr0]     = rs0;
        rs_part[half * 64 + wr0 + 8] = rs1;
        dg_part[half * 64 + wr0]     = dg0;
        dg_part[half * 64 + wr0 + 8] = dg1;
    }
    __syncthreads();

    if (t < 64) {
        float lr = logf(rs_part[t] + rs_part[64 + t]) - (dg_part[t] + dg_part[64 + t]);
        #pragma unroll
        for (int o = 16; o > 0; o >>= 1) lr += __shfl_down_sync(0xffffffffu, lr, o);
        if (lid == 0) red_sh[wid] = lr;
    }
    __syncthreads();
    if (t == 0) atomicAdd(out, (red_sh[0] + red_sh[1]) / (float)n);
}

// ---------------- launch ----------------
extern "C" void kernel_launch(void* const* d_in, const int* in_sizes, int n_in,
                              void* d_out, int out_size) {
    const float* f = (const float*)d_in[0];
    const void*  lab = d_in[1];
    float* out = (float*)d_out;
    int n = in_sizes[1];   // 8192

    cudaFuncSetAttribute(k_main, cudaFuncAttributeMaxDynamicSharedMemorySize, BH_SIZE);

    k_protos<<<CPAD, 256>>>(f, lab, n, out);
    k_main<<<n / 64, 256, BH_SIZE>>>(f, lab, out, n);
}

// round 11
// speedup vs baseline: 2.4230x; 1.1218x over previous
#include <cuda_runtime.h>
#include <cuda_bf16.h>
#include <math.h>
#include <stdint.h>

#define NUM_C   100
#define CPAD    128
#define DIM     256
#define TEMPV   0.7f
#define EPSV    1e-8f
#define NROWS   8192

// B smem: padded row stride 264 bf16 = 528 bytes (conflict-free ldmatrix)
#define BSTRIDE 528
#define BH_SIZE (CPAD * BSTRIDE)       // 67584

// ---------------- device scratch ----------------
__device__ float g_countf[CPAD];
__device__ __align__(16) __nv_bfloat16 g_pTh[CPAD * DIM];   // protoT (bf16)
__device__ int   g_is64;

// ---------------- helpers ----------------
__device__ __forceinline__ uint32_t smem_u32(const void* p) {
    uint32_t a;
    asm("{ .reg .u64 t; cvta.to.shared.u64 t, %1; cvt.u32.u64 %0, t; }" : "=r"(a) : "l"(p));
    return a;
}
__device__ __forceinline__ int get_label(const void* lab, int i, int is64) {
    return is64 ? (int)((const long long*)lab)[i] : ((const int*)lab)[i];
}
__device__ __forceinline__ void split2(float2 v, uint32_t& h, uint32_t& l) {
    __nv_bfloat16 hx = __float2bfloat16(v.x), hy = __float2bfloat16(v.y);
    float rx = v.x - __bfloat162float(hx);
    float ry = v.y - __bfloat162float(hy);
    __nv_bfloat162 H, L;
    H.x = hx; H.y = hy;
    L.x = __float2bfloat16(rx); L.y = __float2bfloat16(ry);
    h = *(uint32_t*)&H;
    l = *(uint32_t*)&L;
}
__device__ __forceinline__ void mma_bf16(float* d, const uint32_t* a, const uint32_t* b) {
    asm volatile(
        "mma.sync.aligned.m16n8k16.row.col.f32.bf16.bf16.f32 "
        "{%0,%1,%2,%3}, {%4,%5,%6,%7}, {%8,%9}, {%0,%1,%2,%3};"
        : "+f"(d[0]), "+f"(d[1]), "+f"(d[2]), "+f"(d[3])
        : "r"(a[0]), "r"(a[1]), "r"(a[2]), "r"(a[3]), "r"(b[0]), "r"(b[1]));
}
#define LDSM4(r, a) \
    asm volatile("ldmatrix.sync.aligned.m8n8.x4.shared.b16 {%0,%1,%2,%3}, [%4];" \
        : "=r"((r)[0]), "=r"((r)[1]), "=r"((r)[2]), "=r"((r)[3]) : "r"(a))
#define CP_ASYNC16(smem, gptr) \
    asm volatile("cp.async.cg.shared.global [%0], [%1], 16;" :: "r"(smem), "l"(gptr) : "memory")
#define CP_WAIT_ALL() \
    asm volatile("cp.async.commit_group;\n cp.async.wait_group 0;" ::: "memory")

// ---------------- K1: one CTA per class — gather, mean, normalize, emit bf16 ----------------
__global__ void __launch_bounds__(256, 1)
k_protos(const float* __restrict__ f, const void* __restrict__ lab, int n, float* out) {
    __shared__ int   list[NROWS];
    __shared__ float wacc[8][DIM];
    __shared__ float red[256];
    __shared__ int   s_m;

    int t = threadIdx.x, wid = t >> 5, lid = t & 31;
    int c = blockIdx.x;
    if (t == 0) s_m = 0;
    __syncthreads();

    const int* l32 = (const int*)lab;
    int fl = 0;
    for (int i = t; i < (n >> 1); i += 256) fl |= l32[2 * i + 1];
    int is64 = (__syncthreads_or(fl) == 0);
    if (c == 0 && t == 0) { g_is64 = is64; out[0] = 0.f; }

    for (int i = t; i < n; i += 256) {
        int li = is64 ? (int)((const long long*)lab)[i] : l32[i];
        if (li == c) { int p = atomicAdd(&s_m, 1); list[p] = i; }
    }
    __syncthreads();
    int m = s_m;

    float s[8];
    #pragma unroll
    for (int i = 0; i < 8; i++) s[i] = 0.f;
    for (int j0 = 0; j0 < m; j0 += 32) {
        float4 va[4], vb[4];
        #pragma unroll
        for (int i = 0; i < 4; i++) {
            int j = j0 + wid * 4 + i;
            if (j < m) {
                const float* fr = f + (size_t)list[j] * DIM;
                va[i] = *(const float4*)(fr + lid * 4);
                vb[i] = *(const float4*)(fr + 128 + lid * 4);
            } else {
                va[i] = make_float4(0.f, 0.f, 0.f, 0.f);
                vb[i] = va[i];
            }
        }
        #pragma unroll
        for (int i = 0; i < 4; i++) {
            s[0] += va[i].x; s[1] += va[i].y; s[2] += va[i].z; s[3] += va[i].w;
            s[4] += vb[i].x; s[5] += vb[i].y; s[6] += vb[i].z; s[7] += vb[i].w;
        }
    }
    wacc[wid][lid * 4 + 0] = s[0];
    wacc[wid][lid * 4 + 1] = s[1];
    wacc[wid][lid * 4 + 2] = s[2];
    wacc[wid][lid * 4 + 3] = s[3];
    wacc[wid][128 + lid * 4 + 0] = s[4];
    wacc[wid][128 + lid * 4 + 1] = s[5];
    wacc[wid][128 + lid * 4 + 2] = s[6];
    wacc[wid][128 + lid * 4 + 3] = s[7];
    __syncthreads();

    float p = 0.f;
    #pragma unroll
    for (int w = 0; w < 8; w++) p += wacc[w][t];
    float cm = (float)m;
    p = p / fmaxf(cm, 1.0f);

    red[t] = p * p;
    __syncthreads();
    for (int st = 128; st > 0; st >>= 1) { if (t < st) red[t] += red[t + st]; __syncthreads(); }
    float nrm = fmaxf(sqrtf(red[0]), EPSV);
    g_pTh[c * DIM + t] = __float2bfloat16(p / (nrm * TEMPV));
    if (t == 0) g_countf[c] = cm;
}

// ---------------- K2: HMMA (fp32A-split x bf16B) + fused contrastive epilogue ----------------
// 128 CTAs x 512 threads (16 warps). Warp w: row-tile (w&3)*16 rows, class quarter (w>>2)*32.
__global__ void __launch_bounds__(512, 1)
k_main(const float* __restrict__ f, const void* __restrict__ lab, float* out, int n) {
    extern __shared__ char dsm[];               // Bh: 67584
    __shared__ float cnt_sh[CPAD];
    __shared__ int   lab_sh[64];
    __shared__ float rs_part[256];              // [quarter*64 + row]
    __shared__ float dg_part[256];
    __shared__ float red_sh[2];

    int t = threadIdx.x, wid = t >> 5, lid = t & 31;
    int g = lid >> 2, tq = lid & 3;
    int wtile = wid & 3, quar = wid >> 2;
    int row0 = blockIdx.x * 64;

    // async-fill protoT smem (padded stride, conflict-free)
    uint32_t dsm_u = smem_u32(dsm);
    {
        const uint4* gh = (const uint4*)g_pTh;
        #pragma unroll
        for (int it = 0; it < 8; it++) {
            int idx = t + it * 512;
            int r = idx >> 5, c = idx & 31;
            CP_ASYNC16(dsm_u + (uint32_t)(r * BSTRIDE + c * 16), gh + idx);
        }
    }
    if (t < CPAD) cnt_sh[t] = g_countf[t];
    if (t < 64) lab_sh[t] = get_label(lab, row0 + t, g_is64);

    int wr0 = wtile * 16 + g;
    const float* fr0 = f + (size_t)(row0 + wr0) * DIM;
    const float* fr1 = fr0 + 8 * DIM;

    // A register ring, prefetch distance 2 (issued while cp.async is in flight)
    float2 abuf[3][4];
    #pragma unroll
    for (int pk = 0; pk < 2; pk++) {
        int k0 = pk * 16 + 2 * tq;
        abuf[pk][0] = *(const float2*)(fr0 + k0);
        abuf[pk][1] = *(const float2*)(fr1 + k0);
        abuf[pk][2] = *(const float2*)(fr0 + k0 + 8);
        abuf[pk][3] = *(const float2*)(fr1 + k0 + 8);
    }
    CP_WAIT_ALL();
    __syncthreads();

    uint32_t Bh_u = dsm_u + (uint32_t)(quar * 32 * BSTRIDE);
    int m8 = lid >> 3, j8 = lid & 7;
    uint32_t laneoff = (uint32_t)(((m8 >> 1) * 8 + j8) * BSTRIDE + (m8 & 1) * 16);

    float acc[4][4];
    #pragma unroll
    for (int i = 0; i < 4; i++) { acc[i][0] = acc[i][1] = acc[i][2] = acc[i][3] = 0.f; }

    float ss0 = 0.f, ss1 = 0.f;                 // row |f|^2 partials (exact fp32)

    #pragma unroll
    for (int kt = 0; kt < 16; kt++) {
        int rb = kt % 3;
        if (kt < 14) {
            int wb = (kt + 2) % 3;
            int k0 = (kt + 2) * 16 + 2 * tq;
            abuf[wb][0] = *(const float2*)(fr0 + k0);
            abuf[wb][1] = *(const float2*)(fr1 + k0);
            abuf[wb][2] = *(const float2*)(fr0 + k0 + 8);
            abuf[wb][3] = *(const float2*)(fr1 + k0 + 8);
        }
        float2 a0 = abuf[rb][0], a1 = abuf[rb][1], a2 = abuf[rb][2], a3 = abuf[rb][3];
        ss0 += a0.x * a0.x + a0.y * a0.y + a2.x * a2.x + a2.y * a2.y;
        ss1 += a1.x * a1.x + a1.y * a1.y + a3.x * a3.x + a3.y * a3.y;

        uint32_t ah[4], al[4];
        split2(a0, ah[0], al[0]);
        split2(a1, ah[1], al[1]);
        split2(a2, ah[2], al[2]);
        split2(a3, ah[3], al[3]);

        uint32_t kb = (uint32_t)(kt * 32) + laneoff;
        uint32_t bh[2][4];
        LDSM4(bh[0], Bh_u + kb);
        LDSM4(bh[1], Bh_u + (uint32_t)(16 * BSTRIDE) + kb);
        #pragma unroll
        for (int ntp = 0; ntp < 2; ntp++) {
            mma_bf16(acc[2 * ntp],     ah, bh[ntp]);
            mma_bf16(acc[2 * ntp + 1], ah, bh[ntp] + 2);
            mma_bf16(acc[2 * ntp],     al, bh[ntp]);
            mma_bf16(acc[2 * ntp + 1], al, bh[ntp] + 2);
        }
    }

    // complete row norms within the quad
    ss0 += __shfl_xor_sync(0xffffffffu, ss0, 1);
    ss0 += __shfl_xor_sync(0xffffffffu, ss0, 2);
    ss1 += __shfl_xor_sync(0xffffffffu, ss1, 1);
    ss1 += __shfl_xor_sync(0xffffffffu, ss1, 2);
    float ifn0 = 1.0f / fmaxf(sqrtf(ss0), EPSV);
    float ifn1 = 1.0f / fmaxf(sqrtf(ss1), EPSV);

    // ---- epilogue: partial row sums over this warp's 32 classes ----
    int chb = quar * 32;
    int lb0 = lab_sh[wr0], lb1 = lab_sh[wr0 + 8];
    float rs0 = 0.f, rs1 = 0.f, dg0 = 0.f, dg1 = 0.f;
    #pragma unroll
    for (int nt = 0; nt < 4; nt++) {
        #pragma unroll
        for (int cc = 0; cc < 2; cc++) {
            int cls = chb + nt * 8 + 2 * tq + cc;
            float cw = cnt_sh[cls];
            float v0 = acc[nt][cc]     * ifn0;
            float v1 = acc[nt][2 + cc] * ifn1;
            rs0 += cw * __expf(v0);
            rs1 += cw * __expf(v1);
            if (cls == lb0) dg0 = v0;
            if (cls == lb1) dg1 = v1;
        }
    }
    #pragma unroll
    for (int o = 1; o <= 2; o <<= 1) {
        rs0 += __shfl_xor_sync(0xffffffffu, rs0, o);
        rs1 += __shfl_xor_sync(0xffffffffu, rs1, o);
        dg0 += __shfl_xor_sync(0xffffffffu, dg0, o);
        dg1 += __shfl_xor_sync(0xffffffffu, dg1, o);
    }
    if (tq == 0) {
        rs_part[quar * 64 + wr0]     = rs0;
        rs_part[quar * 64 + wr0 + 8] = rs1;
        dg_part[quar * 64 + wr0]     = dg0;
        dg_part[quar * 64 + wr0 + 8] = dg1;
    }
    __syncthreads();

    if (t < 64) {
        float rsum = rs_part[t] + rs_part[64 + t] + rs_part[128 + t] + rs_part[192 + t];
        float dsum = dg_part[t] + dg_part[64 + t] + dg_part[128 + t] + dg_part[192 + t];
        float lr = logf(rsum) - dsum;
        #pragma unroll
        for (int o = 16; o > 0; o >>= 1) lr += __shfl_down_sync(0xffffffffu, lr, o);
        if (lid == 0) red_sh[wid] = lr;
    }
    __syncthreads();
    if (t == 0) atomicAdd(out, (red_sh[0] + red_sh[1]) / (float)n);
}

// ---------------- launch ----------------
extern "C" void kernel_launch(void* const* d_in, const int* in_sizes, int n_in,
                              void* d_out, int out_size) {
    const float* f = (const float*)d_in[0];
    const void*  lab = d_in[1];
    float* out = (float*)d_out;
    int n = in_sizes[1];   // 8192

    cudaFuncSetAttribute(k_main, cudaFuncAttributeMaxDynamicSharedMemorySize, BH_SIZE);

    k_protos<<<CPAD, 256>>>(f, lab, n, out);
    k_main<<<n / 64, 512, BH_SIZE>>>(f, lab, out, n);
}

// round 12
// speedup vs baseline: 2.6867x; 1.1088x over previous
#include <cuda_runtime.h>
#include <cuda_bf16.h>
#include <math.h>
#include <stdint.h>

#define NUM_C   100
#define CPAD    128
#define DIM     256
#define TEMPV   0.7f
#define EPSV    1e-8f
#define NROWS   8192

// smem tiles: padded row stride 264 bf16 = 528 bytes (conflict-free ldmatrix)
#define BSTRIDE 528
#define BH_SIZE (CPAD * BSTRIDE)       // 67584
#define AT_SIZE (64 * BSTRIDE)         // 33792 (per A hi/lo tile)
#define SMEM_DYN (BH_SIZE + 2 * AT_SIZE)   // 135168

// ---------------- device scratch ----------------
__device__ float g_countf[CPAD];
__device__ __align__(16) __nv_bfloat16 g_pTh[CPAD * DIM];   // protoT (bf16)
__device__ int   g_is64;

// ---------------- helpers ----------------
__device__ __forceinline__ uint32_t smem_u32(const void* p) {
    uint32_t a;
    asm("{ .reg .u64 t; cvta.to.shared.u64 t, %1; cvt.u32.u64 %0, t; }" : "=r"(a) : "l"(p));
    return a;
}
__device__ __forceinline__ int get_label(const void* lab, int i, int is64) {
    return is64 ? (int)((const long long*)lab)[i] : ((const int*)lab)[i];
}
__device__ __forceinline__ void split2(float2 v, uint32_t& h, uint32_t& l) {
    __nv_bfloat16 hx = __float2bfloat16(v.x), hy = __float2bfloat16(v.y);
    float rx = v.x - __bfloat162float(hx);
    float ry = v.y - __bfloat162float(hy);
    __nv_bfloat162 H, L;
    H.x = hx; H.y = hy;
    L.x = __float2bfloat16(rx); L.y = __float2bfloat16(ry);
    h = *(uint32_t*)&H;
    l = *(uint32_t*)&L;
}
__device__ __forceinline__ void mma_bf16(float* d, const uint32_t* a, const uint32_t* b) {
    asm volatile(
        "mma.sync.aligned.m16n8k16.row.col.f32.bf16.bf16.f32 "
        "{%0,%1,%2,%3}, {%4,%5,%6,%7}, {%8,%9}, {%0,%1,%2,%3};"
        : "+f"(d[0]), "+f"(d[1]), "+f"(d[2]), "+f"(d[3])
        : "r"(a[0]), "r"(a[1]), "r"(a[2]), "r"(a[3]), "r"(b[0]), "r"(b[1]));
}
#define LDSM4(r, a) \
    asm volatile("ldmatrix.sync.aligned.m8n8.x4.shared.b16 {%0,%1,%2,%3}, [%4];" \
        : "=r"((r)[0]), "=r"((r)[1]), "=r"((r)[2]), "=r"((r)[3]) : "r"(a))
#define CP_ASYNC16(smem, gptr) \
    asm volatile("cp.async.cg.shared.global [%0], [%1], 16;" :: "r"(smem), "l"(gptr) : "memory")
#define CP_WAIT_ALL() \
    asm volatile("cp.async.commit_group;\n cp.async.wait_group 0;" ::: "memory")

// ---------------- K1: one CTA per class — gather, mean, normalize, emit bf16 ----------------
__global__ void __launch_bounds__(256, 1)
k_protos(const float* __restrict__ f, const void* __restrict__ lab, int n, float* out) {
    __shared__ int   list[NROWS];
    __shared__ float wacc[8][DIM];
    __shared__ float red[256];
    __shared__ int   s_m;

    int t = threadIdx.x, wid = t >> 5, lid = t & 31;
    int c = blockIdx.x;
    if (t == 0) s_m = 0;
    __syncthreads();

    const int* l32 = (const int*)lab;
    int fl = 0;
    for (int i = t; i < (n >> 1); i += 256) fl |= l32[2 * i + 1];
    int is64 = (__syncthreads_or(fl) == 0);
    if (c == 0 && t == 0) { g_is64 = is64; out[0] = 0.f; }

    for (int i = t; i < n; i += 256) {
        int li = is64 ? (int)((const long long*)lab)[i] : l32[i];
        if (li == c) { int p = atomicAdd(&s_m, 1); list[p] = i; }
    }
    __syncthreads();
    int m = s_m;

    float s[8];
    #pragma unroll
    for (int i = 0; i < 8; i++) s[i] = 0.f;
    for (int j0 = 0; j0 < m; j0 += 32) {
        float4 va[4], vb[4];
        #pragma unroll
        for (int i = 0; i < 4; i++) {
            int j = j0 + wid * 4 + i;
            if (j < m) {
                const float* fr = f + (size_t)list[j] * DIM;
                va[i] = *(const float4*)(fr + lid * 4);
                vb[i] = *(const float4*)(fr + 128 + lid * 4);
            } else {
                va[i] = make_float4(0.f, 0.f, 0.f, 0.f);
                vb[i] = va[i];
            }
        }
        #pragma unroll
        for (int i = 0; i < 4; i++) {
            s[0] += va[i].x; s[1] += va[i].y; s[2] += va[i].z; s[3] += va[i].w;
            s[4] += vb[i].x; s[5] += vb[i].y; s[6] += vb[i].z; s[7] += vb[i].w;
        }
    }
    wacc[wid][lid * 4 + 0] = s[0];
    wacc[wid][lid * 4 + 1] = s[1];
    wacc[wid][lid * 4 + 2] = s[2];
    wacc[wid][lid * 4 + 3] = s[3];
    wacc[wid][128 + lid * 4 + 0] = s[4];
    wacc[wid][128 + lid * 4 + 1] = s[5];
    wacc[wid][128 + lid * 4 + 2] = s[6];
    wacc[wid][128 + lid * 4 + 3] = s[7];
    __syncthreads();

    float p = 0.f;
    #pragma unroll
    for (int w = 0; w < 8; w++) p += wacc[w][t];
    float cm = (float)m;
    p = p / fmaxf(cm, 1.0f);

    red[t] = p * p;
    __syncthreads();
    for (int st = 128; st > 0; st >>= 1) { if (t < st) red[t] += red[t + st]; __syncthreads(); }
    float nrm = fmaxf(sqrtf(red[0]), EPSV);
    g_pTh[c * DIM + t] = __float2bfloat16(p / (nrm * TEMPV));
    if (t == 0) g_countf[c] = cm;
}

// ---------------- K2: all-smem HMMA GEMM + fused contrastive epilogue ----------------
// 128 CTAs x 1024 threads (32 warps). Warp w: row-tile (w&3)*16 rows, class-eighth (w>>2)*16.
__global__ void __launch_bounds__(1024, 1)
k_main(const float* __restrict__ f, const void* __restrict__ lab, float* out, int n) {
    extern __shared__ char dsm[];               // [B: 67584][Ah: 33792][Al: 33792]
    __shared__ float cnt_sh[CPAD];
    __shared__ float invfn_sh[64];
    __shared__ int   lab_sh[64];
    __shared__ float rs_part[512];              // [eighth*64 + row]
    __shared__ float dg_part[512];
    __shared__ float red_sh[2];

    int t = threadIdx.x, wid = t >> 5, lid = t & 31;
    int g = lid >> 2, tq = lid & 3;
    int wtile = wid & 3, eig = wid >> 2;
    int row0 = blockIdx.x * 64;
    uint32_t dsm_u = smem_u32(dsm);

    // async-fill B (protoT) smem
    {
        const uint4* gh = (const uint4*)g_pTh;
        #pragma unroll
        for (int it = 0; it < 4; it++) {
            int idx = t + it * 1024;
            int r = idx >> 5, c = idx & 31;
            CP_ASYNC16(dsm_u + (uint32_t)(r * BSTRIDE + c * 16), gh + idx);
        }
    }

    // convert A tile (64 rows x 256) fp32 -> bf16 hi/lo smem, fused exact row norms
    {
        int arow = t >> 4, c4 = t & 15;
        const float4* fr = (const float4*)(f + (size_t)(row0 + arow) * DIM);
        float ss = 0.f;
        #pragma unroll
        for (int i = 0; i < 4; i++) {
            float4 v = fr[c4 + 16 * i];
            ss += v.x * v.x + v.y * v.y + v.z * v.z + v.w * v.w;
            uint32_t h0, l0, h1, l1;
            split2(make_float2(v.x, v.y), h0, l0);
            split2(make_float2(v.z, v.w), h1, l1);
            int off = arow * BSTRIDE + (c4 + 16 * i) * 8;
            *(uint2*)(dsm + BH_SIZE + off)           = make_uint2(h0, h1);
            *(uint2*)(dsm + BH_SIZE + AT_SIZE + off) = make_uint2(l0, l1);
        }
        #pragma unroll
        for (int o = 1; o <= 8; o <<= 1) ss += __shfl_xor_sync(0xffffffffu, ss, o);
        if ((lid & 15) == 0) invfn_sh[arow] = 1.0f / fmaxf(sqrtf(ss), EPSV);
    }
    if (t < CPAD) cnt_sh[t] = g_countf[t];
    if (t < 64)  lab_sh[t] = get_label(lab, row0 + t, g_is64);
    CP_WAIT_ALL();
    __syncthreads();

    // fragment base addresses
    int m8 = lid >> 3, j8 = lid & 7;
    uint32_t laneA = (uint32_t)(((m8 & 1) * 8 + j8) * BSTRIDE + (m8 >> 1) * 16);
    uint32_t laneB = (uint32_t)(((m8 >> 1) * 8 + j8) * BSTRIDE + (m8 & 1) * 16);
    uint32_t Abase_h = dsm_u + BH_SIZE + (uint32_t)(wtile * 16 * BSTRIDE) + laneA;
    uint32_t Abase_l = Abase_h + AT_SIZE;
    uint32_t Bbase   = dsm_u + (uint32_t)(eig * 16 * BSTRIDE) + laneB;

    float acc0[4] = {0.f, 0.f, 0.f, 0.f};
    float acc1[4] = {0.f, 0.f, 0.f, 0.f};

    #pragma unroll
    for (int kt = 0; kt < 16; kt++) {
        uint32_t ah[4], al[4], bh[4];
        LDSM4(ah, Abase_h + kt * 32);
        LDSM4(bh, Bbase   + kt * 32);
        LDSM4(al, Abase_l + kt * 32);
        mma_bf16(acc0, ah, bh);
        mma_bf16(acc1, ah, bh + 2);
        mma_bf16(acc0, al, bh);
        mma_bf16(acc1, al, bh + 2);
    }

    // ---- epilogue: partial row sums over this warp's 16 classes ----
    int wr0 = wtile * 16 + g;
    int chb = eig * 16;
    float ifn0 = invfn_sh[wr0], ifn1 = invfn_sh[wr0 + 8];
    int   lb0  = lab_sh[wr0],   lb1  = lab_sh[wr0 + 8];
    float rs0 = 0.f, rs1 = 0.f, dg0 = 0.f, dg1 = 0.f;
    #pragma unroll
    for (int nt = 0; nt < 2; nt++) {
        const float* a = nt ? acc1 : acc0;
        #pragma unroll
        for (int cc = 0; cc < 2; cc++) {
            int cls = chb + nt * 8 + 2 * tq + cc;
            float cw = cnt_sh[cls];
            float v0 = a[cc]     * ifn0;
            float v1 = a[2 + cc] * ifn1;
            rs0 += cw * __expf(v0);
            rs1 += cw * __expf(v1);
            if (cls == lb0) dg0 = v0;
            if (cls == lb1) dg1 = v1;
        }
    }
    #pragma unroll
    for (int o = 1; o <= 2; o <<= 1) {
        rs0 += __shfl_xor_sync(0xffffffffu, rs0, o);
        rs1 += __shfl_xor_sync(0xffffffffu, rs1, o);
        dg0 += __shfl_xor_sync(0xffffffffu, dg0, o);
        dg1 += __shfl_xor_sync(0xffffffffu, dg1, o);
    }
    if (tq == 0) {
        rs_part[eig * 64 + wr0]     = rs0;
        rs_part[eig * 64 + wr0 + 8] = rs1;
        dg_part[eig * 64 + wr0]     = dg0;
        dg_part[eig * 64 + wr0 + 8] = dg1;
    }
    __syncthreads();

    if (t < 64) {
        float rsum = 0.f, dsum = 0.f;
        #pragma unroll
        for (int e = 0; e < 8; e++) {
            rsum += rs_part[e * 64 + t];
            dsum += dg_part[e * 64 + t];
        }
        float lr = logf(rsum) - dsum;
        #pragma unroll
        for (int o = 16; o > 0; o >>= 1) lr += __shfl_down_sync(0xffffffffu, lr, o);
        if (lid == 0) red_sh[wid] = lr;
    }
    __syncthreads();
    if (t == 0) atomicAdd(out, (red_sh[0] + red_sh[1]) / (float)n);
}

// ---------------- launch ----------------
extern "C" void kernel_launch(void* const* d_in, const int* in_sizes, int n_in,
                              void* d_out, int out_size) {
    const float* f = (const float*)d_in[0];
    const void*  lab = d_in[1];
    float* out = (float*)d_out;
    int n = in_sizes[1];   // 8192

    cudaFuncSetAttribute(k_main, cudaFuncAttributeMaxDynamicSharedMemorySize, SMEM_DYN);

    k_protos<<<CPAD, 256>>>(f, lab, n, out);
    k_main<<<n / 64, 1024, SMEM_DYN>>>(f, lab, out, n);
}